// round 3
// baseline (speedup 1.0000x reference)
#include <cuda_runtime.h>
#include <cuda_bf16.h>
#include <cstdint>
#include <cstddef>

// ============================================================================
// SNN: 50 timesteps of (GEMM + LIF) x 3 layers, portable sm_103 path:
// mma.sync.m16n8k16 (bf16 -> fp32) + ldmatrix + cp.async (no 'a' features).
// Weights Dekker-split 3-way into bf16 (residual ~2^-26); binary activations
// are bf16-exact, so GEMM precision ~= fp32.
// ============================================================================

#define TSTEPS 50
#define BATCH  256
#define INDIM  1536
#define H1D    4096
#define H2D    4096
#define OUTD   64
#define KSPLIT 16

// ---------------- persistent scratch (device globals) -----------------------
__device__ __align__(128) __nv_bfloat16 g_spk_in[(size_t)TSTEPS * BATCH * INDIM];
__device__ __align__(128) __nv_bfloat16 g_s1[(size_t)BATCH * H1D];
__device__ __align__(128) __nv_bfloat16 g_s2[(size_t)BATCH * H2D];
__device__ __align__(128) float g_mem1[(size_t)BATCH * H1D];
__device__ __align__(128) float g_mem2[(size_t)BATCH * H2D];
__device__ __align__(128) float g_mem3[(size_t)BATCH * OUTD];
__device__ __align__(128) float g_part[(size_t)KSPLIT * BATCH * OUTD];
__device__ __align__(128) __nv_bfloat16 g_W1a[(size_t)H1D * INDIM];
__device__ __align__(128) __nv_bfloat16 g_W1b[(size_t)H1D * INDIM];
__device__ __align__(128) __nv_bfloat16 g_W1c[(size_t)H1D * INDIM];
__device__ __align__(128) __nv_bfloat16 g_W2a[(size_t)H2D * H1D];
__device__ __align__(128) __nv_bfloat16 g_W2b[(size_t)H2D * H1D];
__device__ __align__(128) __nv_bfloat16 g_W2c[(size_t)H2D * H1D];
__device__ __align__(128) __nv_bfloat16 g_W3a[(size_t)OUTD * H2D];
__device__ __align__(128) __nv_bfloat16 g_W3b[(size_t)OUTD * H2D];
__device__ __align__(128) __nv_bfloat16 g_W3c[(size_t)OUTD * H2D];

// ------------------------------ asm helpers ---------------------------------
__device__ __forceinline__ uint32_t smem_u32(const void* p) {
    uint32_t a;
    asm("{ .reg .u64 t; cvta.to.shared.u64 t, %1; cvt.u32.u64 %0, t; }"
        : "=r"(a) : "l"(p));
    return a;
}

__device__ __forceinline__ void cp16(uint32_t smem, const void* gmem) {
    asm volatile("cp.async.cg.shared.global [%0], [%1], 16;"
                 :: "r"(smem), "l"(gmem) : "memory");
}
__device__ __forceinline__ void cp_commit() {
    asm volatile("cp.async.commit_group;" ::: "memory");
}
template<int N>
__device__ __forceinline__ void cp_wait() {
    asm volatile("cp.async.wait_group %0;" :: "n"(N) : "memory");
}

__device__ __forceinline__ void ldsm4(uint32_t (&r)[4], uint32_t addr) {
    asm volatile("ldmatrix.sync.aligned.m8n8.x4.shared.b16 {%0,%1,%2,%3}, [%4];"
                 : "=r"(r[0]), "=r"(r[1]), "=r"(r[2]), "=r"(r[3]) : "r"(addr));
}

__device__ __forceinline__ void mma16816(float (&d)[4], const uint32_t (&a)[4],
                                         uint32_t b0, uint32_t b1) {
    asm volatile(
        "mma.sync.aligned.m16n8k16.row.col.f32.bf16.bf16.f32 "
        "{%0,%1,%2,%3}, {%4,%5,%6,%7}, {%8,%9}, {%0,%1,%2,%3};"
        : "+f"(d[0]), "+f"(d[1]), "+f"(d[2]), "+f"(d[3])
        : "r"(a[0]), "r"(a[1]), "r"(a[2]), "r"(a[3]), "r"(b0), "r"(b1));
}

// ============================================================================
// GEMM (+ LIF epilogue or split-K partial store).
//   D[m,n] = sum_k A[m0+m, k] * (Wa+Wb+Wc)[n0+n, k],  k in [kbase, kbase+nk*64)
// CTA: M=128 x N=64, 256 threads, warps 4(m) x 2(n), warp tile 32x32.
// 4-stage cp.async ring; stage = A(128x64 bf16) + 3x W(64x64 bf16) = 40KB.
// ============================================================================
template<bool LIF>
__global__ void __launch_bounds__(256, 1) gemm_lif(
    const __nv_bfloat16* __restrict__ A, int lda,
    const __nv_bfloat16* __restrict__ Wa,
    const __nv_bfloat16* __restrict__ Wb,
    const __nv_bfloat16* __restrict__ Wc,
    int ldw, int nk,
    const float* __restrict__ bias,
    float* __restrict__ memv,
    __nv_bfloat16* __restrict__ spk, int ldn,
    float* __restrict__ part)
{
    constexpr int S = 4;
    constexpr int ABYTES = 128 * 128;          // 16KB: 128 rows x 64 bf16
    constexpr int BCOMP  = 64 * 128;           // 8KB per weight component
    constexpr int STAGE  = ABYTES + 3 * BCOMP; // 40KB

    extern __shared__ char smem[];
    const uint32_t sbase = smem_u32(smem);

    const int tid  = threadIdx.x;
    const int lane = tid & 31;
    const int wid  = tid >> 5;
    const int m0   = blockIdx.x * 128;
    const int n0   = blockIdx.y * 64;
    const int z    = blockIdx.z;
    const int kbase = z * nk * 64;

    const int warp_m = (wid >> 1) * 32;  // 0,32,64,96
    const int warp_n = (wid & 1) * 32;   // 0,32

    // ---- stage loader -------------------------------------------------------
    auto load_stage = [&](int L) {
        if (L >= nk) return;
        const uint32_t st = sbase + (uint32_t)(L & (S - 1)) * STAGE;
        const int k0 = kbase + L * 64;
        // A: 1024 16B-slots, 4 per thread
        #pragma unroll
        for (int i = 0; i < 4; ++i) {
            const int idx  = tid + i * 256;
            const int row  = idx >> 3;
            const int slot = idx & 7;
            const char* g = (const char*)(A + (size_t)(m0 + row) * lda + k0) + slot * 16;
            cp16(st + (uint32_t)row * 128u + (uint32_t)((slot ^ (row & 7)) << 4), g);
        }
        // B: 3 comps x 512 slots, 2 per thread per comp
        #pragma unroll
        for (int c = 0; c < 3; ++c) {
            const __nv_bfloat16* W = (c == 0) ? Wa : ((c == 1) ? Wb : Wc);
            const uint32_t bb = st + ABYTES + (uint32_t)c * BCOMP;
            #pragma unroll
            for (int i = 0; i < 2; ++i) {
                const int idx  = tid + i * 256;
                const int row  = idx >> 3;
                const int slot = idx & 7;
                const char* g = (const char*)(W + (size_t)(n0 + row) * ldw + k0) + slot * 16;
                cp16(bb + (uint32_t)row * 128u + (uint32_t)((slot ^ (row & 7)) << 4), g);
            }
        }
    };

    // ---- pipeline prologue ---------------------------------------------------
    #pragma unroll
    for (int L = 0; L < S - 1; ++L) { load_stage(L); cp_commit(); }

    float acc[2][4][4];
    #pragma unroll
    for (int mt = 0; mt < 2; ++mt)
        #pragma unroll
        for (int nt = 0; nt < 4; ++nt)
            #pragma unroll
            for (int e = 0; e < 4; ++e) acc[mt][nt][e] = 0.0f;

    // per-thread ldmatrix address components
    const int a_row  = (lane & 7) | ((lane >> 3) & 1) << 3; // row within m16
    const int a_sel  = lane >> 4;                           // k-half (16B slot)
    const int b_row  = (lane & 7) | ((lane >> 4) & 1) << 3; // row within n16
    const int b_sel  = (lane >> 3) & 1;                     // k-half

    // ---- main loop ------------------------------------------------------------
    for (int it = 0; it < nk; ++it) {
        cp_wait<S - 2>();
        __syncthreads();
        load_stage(it + S - 1);
        cp_commit();

        const uint32_t st = sbase + (uint32_t)(it & (S - 1)) * STAGE;

        // A fragments: 2 m-tiles x 4 k-steps
        uint32_t afr[2][4][4];
        #pragma unroll
        for (int mt = 0; mt < 2; ++mt) {
            #pragma unroll
            for (int kk = 0; kk < 4; ++kk) {
                const int row  = warp_m + mt * 16 + a_row;
                const int slot = kk * 2 + a_sel;
                ldsm4(afr[mt][kk],
                      st + (uint32_t)row * 128u + (uint32_t)((slot ^ (row & 7)) << 4));
            }
        }

        #pragma unroll
        for (int c = 0; c < 3; ++c) {
            const uint32_t bb = st + ABYTES + (uint32_t)c * BCOMP;
            // B fragments for this component: 4 k-steps x 2 n16-groups x 4 regs
            uint32_t bfr[4][2][4];
            #pragma unroll
            for (int kk = 0; kk < 4; ++kk) {
                #pragma unroll
                for (int jn = 0; jn < 2; ++jn) {
                    const int row  = warp_n + jn * 16 + b_row;
                    const int slot = kk * 2 + b_sel;
                    ldsm4(bfr[kk][jn],
                          bb + (uint32_t)row * 128u + (uint32_t)((slot ^ (row & 7)) << 4));
                }
            }
            #pragma unroll
            for (int kk = 0; kk < 4; ++kk)
                #pragma unroll
                for (int mt = 0; mt < 2; ++mt)
                    #pragma unroll
                    for (int nt = 0; nt < 4; ++nt)
                        mma16816(acc[mt][nt], afr[mt][kk],
                                 bfr[kk][nt >> 1][(nt & 1) * 2],
                                 bfr[kk][nt >> 1][(nt & 1) * 2 + 1]);
        }
    }

    // ---- epilogue -------------------------------------------------------------
    const int col2 = (lane & 3) * 2;
    const int rowg = lane >> 2;
    #pragma unroll
    for (int mt = 0; mt < 2; ++mt) {
        #pragma unroll
        for (int nt = 0; nt < 4; ++nt) {
            const int n = n0 + warp_n + nt * 8 + col2;
            const int mbase = m0 + warp_m + mt * 16 + rowg;
            if (LIF) {
                const float2 bv = *(const float2*)(bias + n);
                #pragma unroll
                for (int h = 0; h < 2; ++h) {
                    const int m = mbase + h * 8;
                    const size_t off = (size_t)m * ldn + n;
                    float2 mo = *(float2*)(memv + off);
                    const float c0 = acc[mt][nt][h * 2 + 0] + bv.x;
                    const float c1 = acc[mt][nt][h * 2 + 1] + bv.y;
                    const float mn0 = 0.9f * mo.x + c0 - ((mo.x > 1.0f) ? 1.0f : 0.0f);
                    const float mn1 = 0.9f * mo.y + c1 - ((mo.y > 1.0f) ? 1.0f : 0.0f);
                    float2 mw; mw.x = mn0; mw.y = mn1;
                    *(float2*)(memv + off) = mw;
                    __nv_bfloat162 sv;
                    sv.x = __float2bfloat16((mn0 > 1.0f) ? 1.0f : 0.0f);
                    sv.y = __float2bfloat16((mn1 > 1.0f) ? 1.0f : 0.0f);
                    *(__nv_bfloat162*)(spk + off) = sv;
                }
            } else {
                float* po = part + (size_t)z * BATCH * OUTD;
                #pragma unroll
                for (int h = 0; h < 2; ++h) {
                    const int m = mbase + h * 8;
                    float2 pv; pv.x = acc[mt][nt][h * 2 + 0]; pv.y = acc[mt][nt][h * 2 + 1];
                    *(float2*)(po + (size_t)m * OUTD + n) = pv;
                }
            }
        }
    }
}

// ============================================================================
// Small helper kernels
// ============================================================================
__global__ void k_cvt_spk(const float* __restrict__ x, __nv_bfloat16* __restrict__ y, int n) {
    int i = blockIdx.x * blockDim.x + threadIdx.x;
    const int st = gridDim.x * blockDim.x;
    for (; i < n; i += st) y[i] = __float2bfloat16(x[i]);
}

__global__ void k_split_w(const float* __restrict__ W,
                          __nv_bfloat16* __restrict__ a,
                          __nv_bfloat16* __restrict__ b,
                          __nv_bfloat16* __restrict__ c, int n) {
    int i = blockIdx.x * blockDim.x + threadIdx.x;
    const int st = gridDim.x * blockDim.x;
    for (; i < n; i += st) {
        const float w = W[i];
        const __nv_bfloat16 h = __float2bfloat16(w);
        const float r1 = w - __bfloat162float(h);
        const __nv_bfloat16 m = __float2bfloat16(r1);
        const float r2 = r1 - __bfloat162float(m);
        a[i] = h; b[i] = m; c[i] = __float2bfloat16(r2);
    }
}

__global__ void k_zero(float* __restrict__ p, int n) {
    int i = blockIdx.x * blockDim.x + threadIdx.x;
    const int st = gridDim.x * blockDim.x;
    for (; i < n; i += st) p[i] = 0.0f;
}

__global__ void k_reduce3(const float* __restrict__ part,
                          const float* __restrict__ b3,
                          float* __restrict__ mem3,
                          float* __restrict__ out) {
    const int idx = blockIdx.x * blockDim.x + threadIdx.x;   // 16384 threads exact
    const int n = idx & (OUTD - 1);
    float s = b3[n];
    #pragma unroll
    for (int zz = 0; zz < KSPLIT; ++zz)
        s += part[(size_t)zz * BATCH * OUTD + idx];
    const float mo  = mem3[idx];
    const float mn  = 0.9f * mo + s - ((mo > 1.0f) ? 1.0f : 0.0f);
    mem3[idx] = mn;
    out[idx] += ((mn > 1.0f) ? 1.0f : 0.0f);
}

// ============================================================================
// Host launcher
// ============================================================================
extern "C" void kernel_launch(void* const* d_in, const int* in_sizes, int n_in,
                              void* d_out, int out_size) {
    (void)in_sizes; (void)n_in; (void)out_size;

    const float* spike_seq = (const float*)d_in[0];
    const float* W1 = (const float*)d_in[1];
    const float* b1 = (const float*)d_in[2];
    const float* W2 = (const float*)d_in[3];
    const float* b2 = (const float*)d_in[4];
    const float* W3 = (const float*)d_in[5];
    const float* b3 = (const float*)d_in[6];
    float* out = (float*)d_out;

    void *p_spk, *p_s1, *p_s2, *p_m1, *p_m2, *p_m3, *p_part;
    void *p_w1a, *p_w1b, *p_w1c, *p_w2a, *p_w2b, *p_w2c, *p_w3a, *p_w3b, *p_w3c;
    cudaGetSymbolAddress(&p_spk, g_spk_in);
    cudaGetSymbolAddress(&p_s1, g_s1);   cudaGetSymbolAddress(&p_s2, g_s2);
    cudaGetSymbolAddress(&p_m1, g_mem1); cudaGetSymbolAddress(&p_m2, g_mem2);
    cudaGetSymbolAddress(&p_m3, g_mem3); cudaGetSymbolAddress(&p_part, g_part);
    cudaGetSymbolAddress(&p_w1a, g_W1a); cudaGetSymbolAddress(&p_w1b, g_W1b);
    cudaGetSymbolAddress(&p_w1c, g_W1c);
    cudaGetSymbolAddress(&p_w2a, g_W2a); cudaGetSymbolAddress(&p_w2b, g_W2b);
    cudaGetSymbolAddress(&p_w2c, g_W2c);
    cudaGetSymbolAddress(&p_w3a, g_W3a); cudaGetSymbolAddress(&p_w3b, g_W3b);
    cudaGetSymbolAddress(&p_w3c, g_W3c);

    __nv_bfloat16* spkin = (__nv_bfloat16*)p_spk;
    __nv_bfloat16* s1 = (__nv_bfloat16*)p_s1;
    __nv_bfloat16* s2 = (__nv_bfloat16*)p_s2;
    float* mem1 = (float*)p_m1; float* mem2 = (float*)p_m2; float* mem3 = (float*)p_m3;
    float* part = (float*)p_part;
    __nv_bfloat16 *w1a=(__nv_bfloat16*)p_w1a, *w1b=(__nv_bfloat16*)p_w1b, *w1c=(__nv_bfloat16*)p_w1c;
    __nv_bfloat16 *w2a=(__nv_bfloat16*)p_w2a, *w2b=(__nv_bfloat16*)p_w2b, *w2c=(__nv_bfloat16*)p_w2c;
    __nv_bfloat16 *w3a=(__nv_bfloat16*)p_w3a, *w3b=(__nv_bfloat16*)p_w3b, *w3c=(__nv_bfloat16*)p_w3c;

    constexpr int SMEM = 4 * (128 * 128 + 3 * 64 * 128);   // 163840
    static int configured = -1;
    if (configured < 0) {
        cudaFuncSetAttribute(gemm_lif<true>,
                             cudaFuncAttributeMaxDynamicSharedMemorySize, SMEM);
        cudaFuncSetAttribute(gemm_lif<false>,
                             cudaFuncAttributeMaxDynamicSharedMemorySize, SMEM);
        configured = 1;
    }

    // ---- per-call prep ----
    k_cvt_spk<<<4096, 256>>>(spike_seq, spkin, TSTEPS * BATCH * INDIM);
    k_split_w<<<4096, 256>>>(W1, w1a, w1b, w1c, H1D * INDIM);
    k_split_w<<<8192, 256>>>(W2, w2a, w2b, w2c, H2D * H1D);
    k_split_w<<<512,  256>>>(W3, w3a, w3b, w3c, OUTD * H2D);
    k_zero<<<1024, 256>>>(mem1, BATCH * H1D);
    k_zero<<<1024, 256>>>(mem2, BATCH * H2D);
    k_zero<<<64,   256>>>(mem3, BATCH * OUTD);
    k_zero<<<64,   256>>>(out,  BATCH * OUTD);

    // ---- 50 timesteps ----
    for (int t = 0; t < TSTEPS; ++t) {
        const __nv_bfloat16* x_t = spkin + (size_t)t * BATCH * INDIM;

        gemm_lif<true><<<dim3(2, H1D / 64, 1), 256, SMEM>>>(
            x_t, INDIM, w1a, w1b, w1c, INDIM, INDIM / 64,
            b1, mem1, s1, H1D, nullptr);

        gemm_lif<true><<<dim3(2, H2D / 64, 1), 256, SMEM>>>(
            s1, H1D, w2a, w2b, w2c, H1D, H1D / 64,
            b2, mem2, s2, H2D, nullptr);

        gemm_lif<false><<<dim3(2, 1, KSPLIT), 256, SMEM>>>(
            s2, H2D, w3a, w3b, w3c, H2D, (H2D / KSPLIT) / 64,
            nullptr, nullptr, nullptr, 0, part);

        k_reduce3<<<(BATCH * OUTD) / 256, 256>>>(part, b3, mem3, out);
    }
}

// round 4
// speedup vs baseline: 1.3078x; 1.3078x over previous
#include <cuda_runtime.h>
#include <cuda_fp16.h>
#include <cstdint>
#include <cstddef>

// ============================================================================
// SNN: 50 timesteps of (GEMM + LIF) x 3 layers, portable sm_103 path:
// mma.sync.m16n8k16 (f16 -> fp32) + ldmatrix + cp.async.
// Weights split 2-way into fp16 with scaled residual:
//   w = h + m/256,  h = fp16(w), m = fp16(256*(w-h))   (|err| <= ~3.7e-9)
// Binary activations are fp16-exact, so GEMM precision ~= fp32.
// Two fp32 accumulators (hi, mid) combined in the epilogue.
// ============================================================================

#define TSTEPS 50
#define BATCH  256
#define INDIM  1536
#define H1D    4096
#define H2D    4096
#define OUTD   64
#define KSPLIT 16

// ---------------- persistent scratch (device globals) -----------------------
__device__ __align__(128) __half g_spk_in[(size_t)TSTEPS * BATCH * INDIM];
__device__ __align__(128) __half g_s1[(size_t)BATCH * H1D];
__device__ __align__(128) __half g_s2[(size_t)BATCH * H2D];
__device__ __align__(128) float g_mem1[(size_t)BATCH * H1D];
__device__ __align__(128) float g_mem2[(size_t)BATCH * H2D];
__device__ __align__(128) float g_mem3[(size_t)BATCH * OUTD];
__device__ __align__(128) float g_part[(size_t)KSPLIT * BATCH * OUTD];
__device__ __align__(128) __half g_W1a[(size_t)H1D * INDIM];
__device__ __align__(128) __half g_W1b[(size_t)H1D * INDIM];
__device__ __align__(128) __half g_W2a[(size_t)H2D * H1D];
__device__ __align__(128) __half g_W2b[(size_t)H2D * H1D];
__device__ __align__(128) __half g_W3a[(size_t)OUTD * H2D];
__device__ __align__(128) __half g_W3b[(size_t)OUTD * H2D];

// ------------------------------ asm helpers ---------------------------------
__device__ __forceinline__ uint32_t smem_u32(const void* p) {
    uint32_t a;
    asm("{ .reg .u64 t; cvta.to.shared.u64 t, %1; cvt.u32.u64 %0, t; }"
        : "=r"(a) : "l"(p));
    return a;
}

__device__ __forceinline__ void cp16(uint32_t smem, const void* gmem) {
    asm volatile("cp.async.cg.shared.global [%0], [%1], 16;"
                 :: "r"(smem), "l"(gmem) : "memory");
}
__device__ __forceinline__ void cp_commit() {
    asm volatile("cp.async.commit_group;" ::: "memory");
}
template<int N>
__device__ __forceinline__ void cp_wait() {
    asm volatile("cp.async.wait_group %0;" :: "n"(N) : "memory");
}

__device__ __forceinline__ void ldsm4(uint32_t (&r)[4], uint32_t addr) {
    asm volatile("ldmatrix.sync.aligned.m8n8.x4.shared.b16 {%0,%1,%2,%3}, [%4];"
                 : "=r"(r[0]), "=r"(r[1]), "=r"(r[2]), "=r"(r[3]) : "r"(addr));
}

__device__ __forceinline__ void mma16816(float (&d)[4], const uint32_t (&a)[4],
                                         uint32_t b0, uint32_t b1) {
    asm volatile(
        "mma.sync.aligned.m16n8k16.row.col.f32.f16.f16.f32 "
        "{%0,%1,%2,%3}, {%4,%5,%6,%7}, {%8,%9}, {%0,%1,%2,%3};"
        : "+f"(d[0]), "+f"(d[1]), "+f"(d[2]), "+f"(d[3])
        : "r"(a[0]), "r"(a[1]), "r"(a[2]), "r"(a[3]), "r"(b0), "r"(b1));
}

// ============================================================================
// GEMM (+ LIF epilogue or split-K partial store).
//   D[m,n] = sum_k A[m0+m,k] * (Wa + Wb/256)[n0+n,k],  k in [kbase, kbase+nk*64)
// CTA: M=128 x N=64, 256 threads, warps 4(m) x 2(n), warp tile 32x32.
// 5-stage cp.async ring; stage = A(128x64 f16) + 2x W(64x64 f16) = 32KB.
// For LIF kernels, blockIdx.z==1 blocks instead perform the previous step's
// layer-3 split-K reduction + LIF3 + output accumulation (launch fusion).
// ============================================================================
template<bool LIF>
__global__ void __launch_bounds__(256, 1) gemm_lif(
    const __half* __restrict__ A, int lda,
    const __half* __restrict__ Wa,
    const __half* __restrict__ Wb,
    int ldw, int nk,
    const float* __restrict__ bias,
    float* __restrict__ memv,
    __half* __restrict__ spk, int ldn,
    float* __restrict__ part,
    const float* __restrict__ r_part,
    const float* __restrict__ r_b3,
    float* __restrict__ r_mem3,
    float* __restrict__ r_out)
{
    constexpr int S = 5;
    constexpr int ABYTES = 128 * 128;          // 16KB: 128 rows x 64 f16
    constexpr int BCOMP  = 64 * 128;           // 8KB per weight component
    constexpr int STAGE  = ABYTES + 2 * BCOMP; // 32KB

    const int tid  = threadIdx.x;

    // ---- fused reduce blocks (previous step's layer-3 epilogue) -------------
    if (LIF && blockIdx.z == 1) {
        const int bid = (int)(blockIdx.y * 2 + blockIdx.x);
        if (bid < (BATCH * OUTD) / 256) {
            const int idx = bid * 256 + tid;
            const int n = idx & (OUTD - 1);
            float s = r_b3[n];
            #pragma unroll
            for (int zz = 0; zz < KSPLIT; ++zz)
                s += r_part[(size_t)zz * BATCH * OUTD + idx];
            const float mo = r_mem3[idx];
            const float mn = 0.9f * mo + s - ((mo > 1.0f) ? 1.0f : 0.0f);
            r_mem3[idx] = mn;
            r_out[idx] += ((mn > 1.0f) ? 1.0f : 0.0f);
        }
        return;
    }

    extern __shared__ char smem[];
    const uint32_t sbase = smem_u32(smem);

    const int lane = tid & 31;
    const int wid  = tid >> 5;
    const int m0   = blockIdx.x * 128;
    const int n0   = blockIdx.y * 64;
    const int z    = blockIdx.z;
    const int kbase = LIF ? 0 : z * nk * 64;

    const int warp_m = (wid >> 1) * 32;  // 0,32,64,96
    const int warp_n = (wid & 1) * 32;   // 0,32

    // ---- stage loader -------------------------------------------------------
    auto load_stage = [&](int L) {
        if (L >= nk) return;
        const uint32_t st = sbase + (uint32_t)(L % S) * STAGE;
        const int k0 = kbase + L * 64;
        // A: 1024 16B-slots, 4 per thread
        #pragma unroll
        for (int i = 0; i < 4; ++i) {
            const int idx  = tid + i * 256;
            const int row  = idx >> 3;
            const int slot = idx & 7;
            const char* g = (const char*)(A + (size_t)(m0 + row) * lda + k0) + slot * 16;
            cp16(st + (uint32_t)row * 128u + (uint32_t)((slot ^ (row & 7)) << 4), g);
        }
        // B: 2 comps x 512 slots, 2 per thread per comp
        #pragma unroll
        for (int c = 0; c < 2; ++c) {
            const __half* W = (c == 0) ? Wa : Wb;
            const uint32_t bb = st + ABYTES + (uint32_t)c * BCOMP;
            #pragma unroll
            for (int i = 0; i < 2; ++i) {
                const int idx  = tid + i * 256;
                const int row  = idx >> 3;
                const int slot = idx & 7;
                const char* g = (const char*)(W + (size_t)(n0 + row) * ldw + k0) + slot * 16;
                cp16(bb + (uint32_t)row * 128u + (uint32_t)((slot ^ (row & 7)) << 4), g);
            }
        }
    };

    // ---- pipeline prologue ---------------------------------------------------
    #pragma unroll
    for (int L = 0; L < S - 1; ++L) { load_stage(L); cp_commit(); }

    float acc[2][2][4][4];   // [comp][mt][nt][e]
    #pragma unroll
    for (int c = 0; c < 2; ++c)
        #pragma unroll
        for (int mt = 0; mt < 2; ++mt)
            #pragma unroll
            for (int nt = 0; nt < 4; ++nt)
                #pragma unroll
                for (int e = 0; e < 4; ++e) acc[c][mt][nt][e] = 0.0f;

    const int a_row = (lane & 7) | (((lane >> 3) & 1) << 3);
    const int a_sel = lane >> 4;
    const int b_row = (lane & 7) | (((lane >> 4) & 1) << 3);
    const int b_sel = (lane >> 3) & 1;

    // ---- main loop ------------------------------------------------------------
    for (int it = 0; it < nk; ++it) {
        cp_wait<S - 2>();
        __syncthreads();
        load_stage(it + S - 1);
        cp_commit();

        const uint32_t st = sbase + (uint32_t)(it % S) * STAGE;

        uint32_t afr[2][4][4];
        #pragma unroll
        for (int mt = 0; mt < 2; ++mt) {
            #pragma unroll
            for (int kk = 0; kk < 4; ++kk) {
                const int row  = warp_m + mt * 16 + a_row;
                const int slot = kk * 2 + a_sel;
                ldsm4(afr[mt][kk],
                      st + (uint32_t)row * 128u + (uint32_t)((slot ^ (row & 7)) << 4));
            }
        }

        #pragma unroll
        for (int c = 0; c < 2; ++c) {
            const uint32_t bb = st + ABYTES + (uint32_t)c * BCOMP;
            uint32_t bfr[4][2][4];
            #pragma unroll
            for (int kk = 0; kk < 4; ++kk) {
                #pragma unroll
                for (int jn = 0; jn < 2; ++jn) {
                    const int row  = warp_n + jn * 16 + b_row;
                    const int slot = kk * 2 + b_sel;
                    ldsm4(bfr[kk][jn],
                          bb + (uint32_t)row * 128u + (uint32_t)((slot ^ (row & 7)) << 4));
                }
            }
            #pragma unroll
            for (int kk = 0; kk < 4; ++kk)
                #pragma unroll
                for (int mt = 0; mt < 2; ++mt)
                    #pragma unroll
                    for (int nt = 0; nt < 4; ++nt)
                        mma16816(acc[c][mt][nt], afr[mt][kk],
                                 bfr[kk][nt >> 1][(nt & 1) * 2],
                                 bfr[kk][nt >> 1][(nt & 1) * 2 + 1]);
        }
    }

    // ---- epilogue -------------------------------------------------------------
    constexpr float SC = 1.0f / 256.0f;
    const int col2 = (lane & 3) * 2;
    const int rowg = lane >> 2;
    #pragma unroll
    for (int mt = 0; mt < 2; ++mt) {
        #pragma unroll
        for (int nt = 0; nt < 4; ++nt) {
            const int n = n0 + warp_n + nt * 8 + col2;
            const int mbase = m0 + warp_m + mt * 16 + rowg;
            if (LIF) {
                const float2 bv = *(const float2*)(bias + n);
                #pragma unroll
                for (int h = 0; h < 2; ++h) {
                    const int m = mbase + h * 8;
                    const size_t off = (size_t)m * ldn + n;
                    float2 mo = *(float2*)(memv + off);
                    const float c0 = acc[0][mt][nt][h * 2 + 0]
                                   + SC * acc[1][mt][nt][h * 2 + 0] + bv.x;
                    const float c1 = acc[0][mt][nt][h * 2 + 1]
                                   + SC * acc[1][mt][nt][h * 2 + 1] + bv.y;
                    const float mn0 = 0.9f * mo.x + c0 - ((mo.x > 1.0f) ? 1.0f : 0.0f);
                    const float mn1 = 0.9f * mo.y + c1 - ((mo.y > 1.0f) ? 1.0f : 0.0f);
                    float2 mw; mw.x = mn0; mw.y = mn1;
                    *(float2*)(memv + off) = mw;
                    __half2 sv;
                    sv.x = __float2half((mn0 > 1.0f) ? 1.0f : 0.0f);
                    sv.y = __float2half((mn1 > 1.0f) ? 1.0f : 0.0f);
                    *(__half2*)(spk + off) = sv;
                }
            } else {
                float* po = part + (size_t)z * BATCH * OUTD;
                #pragma unroll
                for (int h = 0; h < 2; ++h) {
                    const int m = mbase + h * 8;
                    float2 pv;
                    pv.x = acc[0][mt][nt][h * 2 + 0] + SC * acc[1][mt][nt][h * 2 + 0];
                    pv.y = acc[0][mt][nt][h * 2 + 1] + SC * acc[1][mt][nt][h * 2 + 1];
                    *(float2*)(po + (size_t)m * OUTD + n) = pv;
                }
            }
        }
    }
}

// ============================================================================
// Small helper kernels (exactly 5 prep launches so ncu -s 5 hits gemm1)
// ============================================================================
__global__ void k_cvt_spk(const float* __restrict__ x, __half* __restrict__ y, int n) {
    int i = blockIdx.x * blockDim.x + threadIdx.x;
    const int st = gridDim.x * blockDim.x;
    for (; i < n; i += st) y[i] = __float2half(x[i]);
}

__global__ void k_split_w(const float* __restrict__ W,
                          __half* __restrict__ a,
                          __half* __restrict__ b, int n) {
    int i = blockIdx.x * blockDim.x + threadIdx.x;
    const int st = gridDim.x * blockDim.x;
    for (; i < n; i += st) {
        const float w = W[i];
        const __half h = __float2half_rn(w);
        const float r = w - __half2float(h);
        a[i] = h;
        b[i] = __float2half_rn(r * 256.0f);
    }
}

__global__ void k_zero_all(float* __restrict__ a, int na,
                           float* __restrict__ b, int nb,
                           float* __restrict__ c, int nc,
                           float* __restrict__ d, int nd) {
    const int gid = blockIdx.x * blockDim.x + threadIdx.x;
    const int st = gridDim.x * blockDim.x;
    for (int i = gid; i < na; i += st) a[i] = 0.0f;
    for (int i = gid; i < nb; i += st) b[i] = 0.0f;
    for (int i = gid; i < nc; i += st) c[i] = 0.0f;
    for (int i = gid; i < nd; i += st) d[i] = 0.0f;
}

__global__ void k_reduce3(const float* __restrict__ part,
                          const float* __restrict__ b3,
                          float* __restrict__ mem3,
                          float* __restrict__ out) {
    const int idx = blockIdx.x * blockDim.x + threadIdx.x;   // 16384 threads exact
    const int n = idx & (OUTD - 1);
    float s = b3[n];
    #pragma unroll
    for (int zz = 0; zz < KSPLIT; ++zz)
        s += part[(size_t)zz * BATCH * OUTD + idx];
    const float mo = mem3[idx];
    const float mn = 0.9f * mo + s - ((mo > 1.0f) ? 1.0f : 0.0f);
    mem3[idx] = mn;
    out[idx] += ((mn > 1.0f) ? 1.0f : 0.0f);
}

// ============================================================================
// Host launcher
// ============================================================================
extern "C" void kernel_launch(void* const* d_in, const int* in_sizes, int n_in,
                              void* d_out, int out_size) {
    (void)in_sizes; (void)n_in; (void)out_size;

    const float* spike_seq = (const float*)d_in[0];
    const float* W1 = (const float*)d_in[1];
    const float* b1 = (const float*)d_in[2];
    const float* W2 = (const float*)d_in[3];
    const float* b2 = (const float*)d_in[4];
    const float* W3 = (const float*)d_in[5];
    const float* b3 = (const float*)d_in[6];
    float* out = (float*)d_out;

    void *p_spk, *p_s1, *p_s2, *p_m1, *p_m2, *p_m3, *p_part;
    void *p_w1a, *p_w1b, *p_w2a, *p_w2b, *p_w3a, *p_w3b;
    cudaGetSymbolAddress(&p_spk, g_spk_in);
    cudaGetSymbolAddress(&p_s1, g_s1);   cudaGetSymbolAddress(&p_s2, g_s2);
    cudaGetSymbolAddress(&p_m1, g_mem1); cudaGetSymbolAddress(&p_m2, g_mem2);
    cudaGetSymbolAddress(&p_m3, g_mem3); cudaGetSymbolAddress(&p_part, g_part);
    cudaGetSymbolAddress(&p_w1a, g_W1a); cudaGetSymbolAddress(&p_w1b, g_W1b);
    cudaGetSymbolAddress(&p_w2a, g_W2a); cudaGetSymbolAddress(&p_w2b, g_W2b);
    cudaGetSymbolAddress(&p_w3a, g_W3a); cudaGetSymbolAddress(&p_w3b, g_W3b);

    __half* spkin = (__half*)p_spk;
    __half* s1 = (__half*)p_s1;
    __half* s2 = (__half*)p_s2;
    float* mem1 = (float*)p_m1; float* mem2 = (float*)p_m2; float* mem3 = (float*)p_m3;
    float* part = (float*)p_part;
    __half *w1a = (__half*)p_w1a, *w1b = (__half*)p_w1b;
    __half *w2a = (__half*)p_w2a, *w2b = (__half*)p_w2b;
    __half *w3a = (__half*)p_w3a, *w3b = (__half*)p_w3b;

    constexpr int SMEM = 5 * (128 * 128 + 2 * 64 * 128);   // 163840
    static int configured = -1;
    if (configured < 0) {
        cudaFuncSetAttribute(gemm_lif<true>,
                             cudaFuncAttributeMaxDynamicSharedMemorySize, SMEM);
        cudaFuncSetAttribute(gemm_lif<false>,
                             cudaFuncAttributeMaxDynamicSharedMemorySize, SMEM);
        configured = 1;
    }

    // ---- per-call prep: exactly 5 launches ----
    k_cvt_spk<<<4096, 256>>>(spike_seq, spkin, TSTEPS * BATCH * INDIM);
    k_split_w<<<4096, 256>>>(W1, w1a, w1b, H1D * INDIM);
    k_split_w<<<8192, 256>>>(W2, w2a, w2b, H2D * H1D);
    k_split_w<<<512,  256>>>(W3, w3a, w3b, OUTD * H2D);
    k_zero_all<<<1024, 256>>>(mem1, BATCH * H1D, mem2, BATCH * H2D,
                              mem3, BATCH * OUTD, out, BATCH * OUTD);

    // ---- 50 timesteps ----
    for (int t = 0; t < TSTEPS; ++t) {
        const __half* x_t = spkin + (size_t)t * BATCH * INDIM;

        // gemm1; for t>0, z==1 blocks also run the previous step's layer-3
        // reduction + LIF3 + output accumulation (saves one launch per step)
        gemm_lif<true><<<dim3(2, H1D / 64, (t > 0) ? 2 : 1), 256, SMEM>>>(
            x_t, INDIM, w1a, w1b, INDIM, INDIM / 64,
            b1, mem1, s1, H1D, nullptr,
            part, b3, mem3, out);

        gemm_lif<true><<<dim3(2, H2D / 64, 1), 256, SMEM>>>(
            s1, H1D, w2a, w2b, H1D, H1D / 64,
            b2, mem2, s2, H2D, nullptr,
            nullptr, nullptr, nullptr, nullptr);

        gemm_lif<false><<<dim3(2, 1, KSPLIT), 256, SMEM>>>(
            s2, H2D, w3a, w3b, H2D, (H2D / KSPLIT) / 64,
            nullptr, nullptr, nullptr, 0, part,
            nullptr, nullptr, nullptr, nullptr);
    }

    // final step's layer-3 reduction
    k_reduce3<<<(BATCH * OUTD) / 256, 256>>>(part, b3, mem3, out);
}